// round 15
// baseline (speedup 1.0000x reference)
#include <cuda_runtime.h>
#include <cuda_fp16.h>
#include <cstdint>
#include <cstddef>

// ===================== problem constants =====================
static constexpr int NP      = 50000;     // particles
static constexpr int NPAD    = 50048;     // padded: 782*64
static constexpr int EDG     = 800000;
static constexpr int CAP     = 64;        // slots per receiver (Poisson(16) tail-safe)
static constexpr int KDIM    = 512;       // folded contraction dim: 8 taps * 64 ch
static constexpr int OUTC    = 64;
static constexpr int PD      = 8;         // phase1 cp.async pipeline depth

// scales (exact powers of 2): A*16, B*1024; epilogue * 2^-14
static constexpr float SA      = 16.0f;
static constexpr float SB      = 1024.0f;
static constexpr float INV_SAB = 1.0f / 16384.0f;

// ===================== device scratch (no allocs allowed) =====================
__device__ int    g_deg[NPAD];
__device__ int    g_slotS[(size_t)NPAD * CAP];        // sender per slot
__device__ float4 g_wp[(size_t)NPAD * CAP * 2];       // folded weights, 2 float4 per slot
__device__ __align__(128) __half g_Ah[(size_t)NPAD * KDIM];   // fp16-hi of A*16, [row][512]
__device__ __align__(128) __half g_Al[(size_t)NPAD * KDIM];   // fp16-lo residual
__device__ __align__(128) __half g_Bh[OUTC * KDIM];           // fp16-hi of Kfold^T*1024, [n][k]
__device__ __align__(128) __half g_Bl[OUTC * KDIM];           // fp16-lo residual

// ===================== helpers =====================
__device__ __forceinline__ uint32_t smem_u32(const void* p) {
    return (uint32_t)__cvta_generic_to_shared(p);
}

__device__ __forceinline__ void mma16(float* c, const uint32_t* a, const uint32_t* b) {
    asm volatile(
        "mma.sync.aligned.m16n8k16.row.col.f32.f16.f16.f32 "
        "{%0,%1,%2,%3}, {%4,%5,%6,%7}, {%8,%9}, {%0,%1,%2,%3};"
        : "+f"(c[0]), "+f"(c[1]), "+f"(c[2]), "+f"(c[3])
        : "r"(a[0]), "r"(a[1]), "r"(a[2]), "r"(a[3]), "r"(b[0]), "r"(b[1]));
}

__device__ __forceinline__ void ldsm4(uint32_t* r, uint32_t addr) {
    asm volatile("ldmatrix.sync.aligned.m8n8.x4.shared.b16 {%0,%1,%2,%3}, [%4];"
                 : "=r"(r[0]), "=r"(r[1]), "=r"(r[2]), "=r"(r[3]) : "r"(addr));
}

// ===================== kernel 1: zero degree counters + build folded B (fp16 hi/lo) =====================
__global__ void k_prep(const float* __restrict__ ker) {
    int i = blockIdx.x * blockDim.x + threadIdx.x;
    if (i < NPAD) g_deg[i] = 0;
    if (i < KDIM * OUTC) {
        int n = i / KDIM;
        int k = i % KDIM;
        int t = k / 64, ic = k % 64;
        int x = t / 4, y = t % 4;
        float v;
        if (y < 2) v = ker[(((x * 2 + y) * 64 + ic) * 64) + n];
        else       v = -ker[((((3 - x) * 2 + (3 - y)) * 64 + ic) * 64) + n];
        float vs = v * SB;
        __half h = __float2half_rn(vs);
        __half l = __float2half_rn(vs - __half2float(h));
        g_Bh[n * KDIM + k] = h;
        g_Bl[n * KDIM + k] = l;
    }
}

// ===================== kernel 2: bucket edges + precompute folded weights =====================
__global__ void k_fill(const int* __restrict__ recv, const int* __restrict__ snd,
                       const float* __restrict__ rp, const float* __restrict__ ws_p) {
    int e = blockIdx.x * blockDim.x + threadIdx.x;
    if (e >= EDG) return;
    int r = recv[e];
    int slot = atomicAdd(&g_deg[r], 1);
    if (slot >= CAP) return;

    float inv_ws = 1.0f / (*ws_p);
    float2 p = ((const float2*)rp)[e];
    float ux = fminf(fmaxf(p.x * inv_ws, -1.f), 1.f);
    float uy = fminf(fmaxf(p.y * inv_ws, -1.f), 1.f);
    float gx = (ux + 1.f) * 1.5f;
    float gy = (uy + 1.f) * 1.5f;
    float x0 = fminf(fmaxf(floorf(gx), 0.f), 2.f);
    float y0 = fminf(fmaxf(floorf(gy), 0.f), 2.f);
    float fx = gx - x0, fy = gy - y0;
    int x0i = (int)x0, y0i = (int)y0;
    float r2 = ux * ux + uy * uy;
    float win = fmaxf(1.f - r2, 0.f);
    win = win * win * win;

    float wx[4], wy[4];
    #pragma unroll
    for (int j = 0; j < 4; j++) {
        wx[j] = (j == x0i) ? (1.f - fx) * win : ((j == x0i + 1) ? fx * win : 0.f);
        wy[j] = (j == y0i) ? (1.f - fy)       : ((j == y0i + 1) ? fy       : 0.f);
    }
    float wf[8];
    #pragma unroll
    for (int f = 0; f < 8; f++) {
        int xf = f >> 2, yf = f & 3;
        wf[f] = wx[xf] * wy[yf] - wx[3 - xf] * wy[3 - yf];
    }
    size_t si = (size_t)r * CAP + slot;
    g_slotS[si] = snd[e];
    g_wp[si * 2 + 0] = make_float4(wf[0], wf[1], wf[2], wf[3]);
    g_wp[si * 2 + 1] = make_float4(wf[4], wf[5], wf[6], wf[7]);
}

// ===================== kernel 3: per-receiver aggregation, f32x2 packed FMA =====================
// acc layout: acc2[0..3] = tap-pairs (0,1),(2,3),(4,5),(6,7) for channel c0 = 2*lane,
//             acc2[4..7] = same tap-pairs for channel c1 = 2*lane+1.
// Weights g_wp are tap-consecutive -> directly usable as f32x2 operands.
__global__ void __launch_bounds__(64) k_phase1(const float* __restrict__ feat) {
    __shared__ float sFeat[2][PD][64];
    __shared__ float sW[2][PD][8];

    int warp = threadIdx.x >> 5, lane = threadIdx.x & 31;
    int r = blockIdx.x * 2 + warp;          // grid = NPAD/2 exactly
    int nd = min(g_deg[r], CAP);            // uniform across warp
    size_t base = (size_t)r * CAP;

    int sl = (lane < nd)      ? g_slotS[base + lane]      : 0;
    int sh = (32 + lane < nd) ? g_slotS[base + 32 + lane] : 0;

    unsigned long long acc2[8];
    #pragma unroll
    for (int j = 0; j < 8; j++) acc2[j] = 0ull;

    #define ISSUE(e) do {                                                        \
        int _e = (e);                                                            \
        if (_e < nd) {                                                           \
            int _j = _e & (PD - 1);                                              \
            int _s = __shfl_sync(0xFFFFFFFFu, (_e < 32) ? sl : sh, _e & 31);     \
            if (lane < 16) {                                                     \
                const float4* _src = (const float4*)(feat + (size_t)_s * 64) + lane; \
                uint32_t _dst = smem_u32(&sFeat[warp][_j][lane * 4]);            \
                asm volatile("cp.async.ca.shared.global [%0], [%1], 16;"         \
                             :: "r"(_dst), "l"(_src) : "memory");                \
            } else if (lane < 18) {                                              \
                const float4* _src = &g_wp[(base + _e) * 2 + (lane - 16)];       \
                uint32_t _dst = smem_u32(&sW[warp][_j][(lane - 16) * 4]);        \
                asm volatile("cp.async.ca.shared.global [%0], [%1], 16;"         \
                             :: "r"(_dst), "l"(_src) : "memory");                \
            }                                                                    \
        }                                                                        \
        asm volatile("cp.async.commit_group;" ::: "memory");                     \
    } while (0)

    #define CONSUME(e) do {                                                      \
        int _jb = (e) & (PD - 1);                                                \
        float2 f = *(const float2*)&sFeat[warp][_jb][lane * 2];                  \
        const unsigned long long* w2 =                                           \
            (const unsigned long long*)&sW[warp][_jb][0];                        \
        unsigned long long w0 = w2[0], w1 = w2[1], w2_ = w2[2], w3 = w2[3];      \
        unsigned long long f0, f1;                                               \
        asm("mov.b64 %0, {%1, %1};" : "=l"(f0) : "r"(__float_as_uint(f.x)));     \
        asm("mov.b64 %0, {%1, %1};" : "=l"(f1) : "r"(__float_as_uint(f.y)));     \
        asm("fma.rn.f32x2 %0, %1, %2, %0;" : "+l"(acc2[0]) : "l"(w0),  "l"(f0)); \
        asm("fma.rn.f32x2 %0, %1, %2, %0;" : "+l"(acc2[1]) : "l"(w1),  "l"(f0)); \
        asm("fma.rn.f32x2 %0, %1, %2, %0;" : "+l"(acc2[2]) : "l"(w2_), "l"(f0)); \
        asm("fma.rn.f32x2 %0, %1, %2, %0;" : "+l"(acc2[3]) : "l"(w3),  "l"(f0)); \
        asm("fma.rn.f32x2 %0, %1, %2, %0;" : "+l"(acc2[4]) : "l"(w0),  "l"(f1)); \
        asm("fma.rn.f32x2 %0, %1, %2, %0;" : "+l"(acc2[5]) : "l"(w1),  "l"(f1)); \
        asm("fma.rn.f32x2 %0, %1, %2, %0;" : "+l"(acc2[6]) : "l"(w2_), "l"(f1)); \
        asm("fma.rn.f32x2 %0, %1, %2, %0;" : "+l"(acc2[7]) : "l"(w3),  "l"(f1)); \
    } while (0)

    #pragma unroll
    for (int j = 0; j < PD; j++) ISSUE(j);

    int e = 0;
    for (; e + 3 < nd; e += 4) {
        asm volatile("cp.async.wait_group %0;" :: "n"(PD - 4) : "memory");
        __syncwarp();
        CONSUME(e);
        CONSUME(e + 1);
        CONSUME(e + 2);
        CONSUME(e + 3);
        __syncwarp();
        ISSUE(e + PD);
        ISSUE(e + PD + 1);
        ISSUE(e + PD + 2);
        ISSUE(e + PD + 3);
    }
    if (e < nd) {
        asm volatile("cp.async.wait_group 0;" ::: "memory");
        __syncwarp();
        for (; e < nd; e++) CONSUME(e);
    }
    #undef ISSUE
    #undef CONSUME

    // tail: unpack tap-pairs, scale by SA, split to fp16 hi/lo, store half2 (c0,c1)
    __half2* dhi = (__half2*)g_Ah + (((size_t)r * KDIM) >> 1) + lane;
    __half2* dlo = (__half2*)g_Al + (((size_t)r * KDIM) >> 1) + lane;
    #pragma unroll
    for (int t = 0; t < 8; t++) {
        uint32_t c0b, c1b, dumm;
        if (t & 1) {
            asm("mov.b64 {%0, %1}, %2;" : "=r"(dumm), "=r"(c0b) : "l"(acc2[t >> 1]));
            asm("mov.b64 {%0, %1}, %2;" : "=r"(dumm), "=r"(c1b) : "l"(acc2[4 + (t >> 1)]));
        } else {
            asm("mov.b64 {%0, %1}, %2;" : "=r"(c0b), "=r"(dumm) : "l"(acc2[t >> 1]));
            asm("mov.b64 {%0, %1}, %2;" : "=r"(c1b), "=r"(dumm) : "l"(acc2[4 + (t >> 1)]));
        }
        float v0 = __uint_as_float(c0b) * SA, v1 = __uint_as_float(c1b) * SA;
        __half h0 = __float2half_rn(v0);
        __half h1 = __float2half_rn(v1);
        __half l0 = __float2half_rn(v0 - __half2float(h0));
        __half l1 = __float2half_rn(v1 - __half2float(h1));
        dhi[t * 32] = __halves2half2(h0, h1);
        dlo[t * 32] = __halves2half2(l0, l1);
    }
}

// ===================== kernel 4: fp16 3-pass mma GEMM, 4-stage cp.async multistage (R13 config) =====================
// out[NPAD(64/CTA), 64] = (Ah+Al)(Bh+Bl)^T * 2^-14 + bias  (drop Al*Bl)
// 8 warps as 2(M) x 4(N); warp tile 32x16; KC=32 (2 k16-steps), 16 chunks, 4 stages
static constexpr int KC    = 32;               // k (halfs) per chunk
static constexpr int HST   = 40;               // smem row stride (halfs): 80B, conflict-free
static constexpr int F_MAT = 64 * HST;         // 2560 halfs per matrix tile
static constexpr int F_STG = 4 * F_MAT;        // Ah, Al, Bh, Bl
static constexpr int NCH   = KDIM / KC;        // 16 chunks
static constexpr int GEMM_SMEM = 4 * F_STG * 2;   // 81920 bytes -> 2 CTAs/SM

__global__ void __launch_bounds__(256, 2) k_gemm(const float* __restrict__ bias,
                                                 float* __restrict__ out) {
    extern __shared__ __half smh[];

    int tid = threadIdx.x;
    int warp = tid >> 5, lane = tid & 31;
    int gid = lane >> 2, tig = lane & 3;
    int warpM = warp >> 2, warpN = warp & 3;
    int m_base = warpM * 32;
    int n_base = warpN * 16;
    int m0 = blockIdx.x * 64;

    // ldmatrix lane->tile mapping
    int t3  = lane >> 3, rin = lane & 7;
    int a_row = ((t3 & 1) << 3) + rin;
    int a_k   = (t3 >> 1) << 3;
    int b_row = ((t3 >> 1) << 3) + rin;
    int b_k   = (t3 & 1) << 3;

    // staging: per matrix 64 rows x 64B; 256 threads -> 1 cp.async each
    int srow = tid >> 2, so8 = (tid & 3) * 8;

    float acc[2][2][4];
    #pragma unroll
    for (int mt = 0; mt < 2; mt++)
        #pragma unroll
        for (int nt = 0; nt < 2; nt++)
            #pragma unroll
            for (int j = 0; j < 4; j++) acc[mt][nt][j] = 0.f;

    #define STAGE(kc) do {                                                       \
        if ((kc) < NCH) {                                                        \
            __half* _st = smh + ((kc) & 3) * F_STG;                              \
            int _go = (kc) * KC + so8;                                           \
            uint32_t _so = srow * HST + so8;                                     \
            asm volatile("cp.async.ca.shared.global [%0], [%1], 16;"             \
                :: "r"(smem_u32(_st + _so)),                                     \
                   "l"(g_Ah + (size_t)(m0 + srow) * KDIM + _go) : "memory");     \
            asm volatile("cp.async.ca.shared.global [%0], [%1], 16;"             \
                :: "r"(smem_u32(_st + F_MAT + _so)),                             \
                   "l"(g_Al + (size_t)(m0 + srow) * KDIM + _go) : "memory");     \
            asm volatile("cp.async.ca.shared.global [%0], [%1], 16;"             \
                :: "r"(smem_u32(_st + 2 * F_MAT + _so)),                         \
                   "l"(g_Bh + srow * KDIM + _go) : "memory");                    \
            asm volatile("cp.async.ca.shared.global [%0], [%1], 16;"             \
                :: "r"(smem_u32(_st + 3 * F_MAT + _so)),                         \
                   "l"(g_Bl + srow * KDIM + _go) : "memory");                    \
        }                                                                        \
        asm volatile("cp.async.commit_group;" ::: "memory");                     \
    } while (0)

    // ---- prologue: stage chunks 0,1,2 ----
    STAGE(0);
    STAGE(1);
    STAGE(2);

    #pragma unroll 1
    for (int kc = 0; kc < NCH; kc++) {
        asm volatile("cp.async.wait_group 2;" ::: "memory");   // chunk kc complete
        __syncthreads();
        STAGE(kc + 3);                                         // slot (kc+3)&3, free

        const __half* st  = smh + (kc & 3) * F_STG;
        const __half* pAh = st;
        const __half* pAl = st + F_MAT;
        const __half* pBh = st + 2 * F_MAT;
        const __half* pBl = st + 3 * F_MAT;

        #pragma unroll
        for (int ks = 0; ks < 2; ks++) {
            int k0 = ks * 16;
            uint32_t ah[2][4], al[2][4], bh[4], bl[4];
            #pragma unroll
            for (int mt = 0; mt < 2; mt++) {
                int off = (m_base + mt * 16 + a_row) * HST + k0 + a_k;
                ldsm4(ah[mt], smem_u32(pAh + off));
                ldsm4(al[mt], smem_u32(pAl + off));
            }
            {
                int off = (n_base + b_row) * HST + k0 + b_k;
                ldsm4(bh, smem_u32(pBh + off));
                ldsm4(bl, smem_u32(pBl + off));
            }
            #pragma unroll
            for (int mt = 0; mt < 2; mt++)
                #pragma unroll
                for (int nt = 0; nt < 2; nt++) {
                    mma16(acc[mt][nt], ah[mt], &bh[nt * 2]);
                    mma16(acc[mt][nt], al[mt], &bh[nt * 2]);
                    mma16(acc[mt][nt], ah[mt], &bl[nt * 2]);
                }
        }
    }
    #undef STAGE

    // ---- epilogue: un-scale + bias + store ----
    #pragma unroll
    for (int mt = 0; mt < 2; mt++) {
        int r  = m0 + m_base + mt * 16 + gid;
        int r8 = r + 8;
        #pragma unroll
        for (int nt = 0; nt < 2; nt++) {
            int c = n_base + nt * 8 + tig * 2;
            float b0 = __ldg(bias + c), b1 = __ldg(bias + c + 1);
            if (r < NP) {
                float2 v = make_float2(acc[mt][nt][0] * INV_SAB + b0,
                                       acc[mt][nt][1] * INV_SAB + b1);
                *(float2*)(out + (size_t)r * 64 + c) = v;
            }
            if (r8 < NP) {
                float2 v = make_float2(acc[mt][nt][2] * INV_SAB + b0,
                                       acc[mt][nt][3] * INV_SAB + b1);
                *(float2*)(out + (size_t)r8 * 64 + c) = v;
            }
        }
    }
}

// ===================== launch =====================
extern "C" void kernel_launch(void* const* d_in, const int* in_sizes, int n_in,
                              void* d_out, int out_size) {
    const float* feat = (const float*)d_in[0];
    const int*   recv = (const int*)d_in[1];
    const float* rp   = (const float*)d_in[2];
    const float* ws   = (const float*)d_in[3];
    const int*   snd  = (const int*)d_in[4];
    const float* ker  = (const float*)d_in[5];
    const float* bias = (const float*)d_in[6];
    float* out = (float*)d_out;

    cudaFuncSetAttribute(k_gemm, cudaFuncAttributeMaxDynamicSharedMemorySize, GEMM_SMEM);

    k_prep<<<(NPAD + 255) / 256, 256>>>(ker);
    k_fill<<<(EDG + 255) / 256, 256>>>(recv, snd, rp, ws);
    k_phase1<<<NPAD / 2, 64>>>(feat);
    k_gemm<<<NPAD / 64, 256, GEMM_SMEM>>>(bias, out);
}

// round 16
// speedup vs baseline: 1.1094x; 1.1094x over previous
#include <cuda_runtime.h>
#include <cuda_fp16.h>
#include <cstdint>
#include <cstddef>

// ===================== problem constants =====================
static constexpr int NP      = 50000;     // particles
static constexpr int NPAD    = 50048;     // padded: 782*64
static constexpr int EDG     = 800000;
static constexpr int CAP     = 64;        // slots per receiver (Poisson(16) tail-safe)
static constexpr int KDIM    = 512;       // folded contraction dim: 8 taps * 64 ch
static constexpr int OUTC    = 64;
static constexpr int PD      = 16;        // phase1 cp.async pipeline depth

// scales (exact powers of 2): A*16, B*1024; epilogue * 2^-14
static constexpr float SA      = 16.0f;
static constexpr float SB      = 1024.0f;
static constexpr float INV_SAB = 1.0f / 16384.0f;

// ===================== device scratch (no allocs allowed) =====================
__device__ int    g_deg[NPAD];
__device__ int    g_slotS[(size_t)NPAD * CAP];        // sender per slot
__device__ float4 g_wp[(size_t)NPAD * CAP * 2];       // folded weights, 2 float4 per slot
__device__ __align__(128) __half g_Ah[(size_t)NPAD * KDIM];   // fp16-hi of A*16, [row][512]
__device__ __align__(128) __half g_Al[(size_t)NPAD * KDIM];   // fp16-lo residual
__device__ __align__(128) __half g_Bh[OUTC * KDIM];           // fp16-hi of Kfold^T*1024, [n][k]
__device__ __align__(128) __half g_Bl[OUTC * KDIM];           // fp16-lo residual

// ===================== helpers =====================
__device__ __forceinline__ uint32_t smem_u32(const void* p) {
    return (uint32_t)__cvta_generic_to_shared(p);
}

__device__ __forceinline__ void mma16(float* c, const uint32_t* a, const uint32_t* b) {
    asm volatile(
        "mma.sync.aligned.m16n8k16.row.col.f32.f16.f16.f32 "
        "{%0,%1,%2,%3}, {%4,%5,%6,%7}, {%8,%9}, {%0,%1,%2,%3};"
        : "+f"(c[0]), "+f"(c[1]), "+f"(c[2]), "+f"(c[3])
        : "r"(a[0]), "r"(a[1]), "r"(a[2]), "r"(a[3]), "r"(b[0]), "r"(b[1]));
}

__device__ __forceinline__ void ldsm4(uint32_t* r, uint32_t addr) {
    asm volatile("ldmatrix.sync.aligned.m8n8.x4.shared.b16 {%0,%1,%2,%3}, [%4];"
                 : "=r"(r[0]), "=r"(r[1]), "=r"(r[2]), "=r"(r[3]) : "r"(addr));
}

// ===================== kernel 1: zero degree counters + build folded B (fp16 hi/lo) =====================
__global__ void k_prep(const float* __restrict__ ker) {
    int i = blockIdx.x * blockDim.x + threadIdx.x;
    if (i < NPAD) g_deg[i] = 0;
    if (i < KDIM * OUTC) {
        int n = i / KDIM;
        int k = i % KDIM;
        int t = k / 64, ic = k % 64;
        int x = t / 4, y = t % 4;
        float v;
        if (y < 2) v = ker[(((x * 2 + y) * 64 + ic) * 64) + n];
        else       v = -ker[((((3 - x) * 2 + (3 - y)) * 64 + ic) * 64) + n];
        float vs = v * SB;
        __half h = __float2half_rn(vs);
        __half l = __float2half_rn(vs - __half2float(h));
        g_Bh[n * KDIM + k] = h;
        g_Bl[n * KDIM + k] = l;
    }
}

// ===================== kernel 2: bucket edges + precompute folded weights =====================
__global__ void k_fill(const int* __restrict__ recv, const int* __restrict__ snd,
                       const float* __restrict__ rp, const float* __restrict__ ws_p) {
    int e = blockIdx.x * blockDim.x + threadIdx.x;
    if (e >= EDG) return;
    int r = recv[e];
    int slot = atomicAdd(&g_deg[r], 1);
    if (slot >= CAP) return;

    float inv_ws = 1.0f / (*ws_p);
    float2 p = ((const float2*)rp)[e];
    float ux = fminf(fmaxf(p.x * inv_ws, -1.f), 1.f);
    float uy = fminf(fmaxf(p.y * inv_ws, -1.f), 1.f);
    float gx = (ux + 1.f) * 1.5f;
    float gy = (uy + 1.f) * 1.5f;
    float x0 = fminf(fmaxf(floorf(gx), 0.f), 2.f);
    float y0 = fminf(fmaxf(floorf(gy), 0.f), 2.f);
    float fx = gx - x0, fy = gy - y0;
    int x0i = (int)x0, y0i = (int)y0;
    float r2 = ux * ux + uy * uy;
    float win = fmaxf(1.f - r2, 0.f);
    win = win * win * win;

    float wx[4], wy[4];
    #pragma unroll
    for (int j = 0; j < 4; j++) {
        wx[j] = (j == x0i) ? (1.f - fx) * win : ((j == x0i + 1) ? fx * win : 0.f);
        wy[j] = (j == y0i) ? (1.f - fy)       : ((j == y0i + 1) ? fy       : 0.f);
    }
    float wf[8];
    #pragma unroll
    for (int f = 0; f < 8; f++) {
        int xf = f >> 2, yf = f & 3;
        wf[f] = wx[xf] * wy[yf] - wx[3 - xf] * wy[3 - yf];
    }
    size_t si = (size_t)r * CAP + slot;
    g_slotS[si] = snd[e];
    g_wp[si * 2 + 0] = make_float4(wf[0], wf[1], wf[2], wf[3]);
    g_wp[si * 2 + 1] = make_float4(wf[4], wf[5], wf[6], wf[7]);
}

// ===================== kernel 3: per-receiver aggregation; emits fp16 hi/lo A*16 =====================
// PD=16 ring, consume-8/issue-8 per wait: half the sync overhead of R13, 8-edge lookahead.
__global__ void __launch_bounds__(64) k_phase1(const float* __restrict__ feat) {
    __shared__ float sFeat[2][PD][64];
    __shared__ float sW[2][PD][8];

    int warp = threadIdx.x >> 5, lane = threadIdx.x & 31;
    int r = blockIdx.x * 2 + warp;          // grid = NPAD/2 exactly
    int nd = min(g_deg[r], CAP);            // uniform across warp
    size_t base = (size_t)r * CAP;

    int sl = (lane < nd)      ? g_slotS[base + lane]      : 0;
    int sh = (32 + lane < nd) ? g_slotS[base + 32 + lane] : 0;

    float acc[16];
    #pragma unroll
    for (int j = 0; j < 16; j++) acc[j] = 0.f;

    #define ISSUE(e) do {                                                        \
        int _e = (e);                                                            \
        if (_e < nd) {                                                           \
            int _j = _e & (PD - 1);                                              \
            int _s = __shfl_sync(0xFFFFFFFFu, (_e < 32) ? sl : sh, _e & 31);     \
            if (lane < 16) {                                                     \
                const float4* _src = (const float4*)(feat + (size_t)_s * 64) + lane; \
                uint32_t _dst = smem_u32(&sFeat[warp][_j][lane * 4]);            \
                asm volatile("cp.async.ca.shared.global [%0], [%1], 16;"         \
                             :: "r"(_dst), "l"(_src) : "memory");                \
            } else if (lane < 18) {                                              \
                const float4* _src = &g_wp[(base + _e) * 2 + (lane - 16)];       \
                uint32_t _dst = smem_u32(&sW[warp][_j][(lane - 16) * 4]);        \
                asm volatile("cp.async.ca.shared.global [%0], [%1], 16;"         \
                             :: "r"(_dst), "l"(_src) : "memory");                \
            }                                                                    \
        }                                                                        \
        asm volatile("cp.async.commit_group;" ::: "memory");                     \
    } while (0)

    #define CONSUME(e) do {                                                      \
        int _jb = (e) & (PD - 1);                                                \
        float2 f  = *(const float2*)&sFeat[warp][_jb][lane * 2];                 \
        float4 w0 = *(const float4*)&sW[warp][_jb][0];                           \
        float4 w1 = *(const float4*)&sW[warp][_jb][4];                           \
        acc[0]  += w0.x * f.x;  acc[1]  += w0.x * f.y;                           \
        acc[2]  += w0.y * f.x;  acc[3]  += w0.y * f.y;                           \
        acc[4]  += w0.z * f.x;  acc[5]  += w0.z * f.y;                           \
        acc[6]  += w0.w * f.x;  acc[7]  += w0.w * f.y;                           \
        acc[8]  += w1.x * f.x;  acc[9]  += w1.x * f.y;                           \
        acc[10] += w1.y * f.x;  acc[11] += w1.y * f.y;                           \
        acc[12] += w1.z * f.x;  acc[13] += w1.z * f.y;                           \
        acc[14] += w1.w * f.x;  acc[15] += w1.w * f.y;                           \
    } while (0)

    #pragma unroll
    for (int j = 0; j < PD; j++) ISSUE(j);

    int e = 0;
    for (; e + 7 < nd; e += 8) {
        asm volatile("cp.async.wait_group %0;" :: "n"(PD - 8) : "memory");
        __syncwarp();
        CONSUME(e);
        CONSUME(e + 1);
        CONSUME(e + 2);
        CONSUME(e + 3);
        CONSUME(e + 4);
        CONSUME(e + 5);
        CONSUME(e + 6);
        CONSUME(e + 7);
        __syncwarp();
        ISSUE(e + PD);
        ISSUE(e + PD + 1);
        ISSUE(e + PD + 2);
        ISSUE(e + PD + 3);
        ISSUE(e + PD + 4);
        ISSUE(e + PD + 5);
        ISSUE(e + PD + 6);
        ISSUE(e + PD + 7);
    }
    if (e < nd) {
        asm volatile("cp.async.wait_group 0;" ::: "memory");
        __syncwarp();
        for (; e < nd; e++) CONSUME(e);
    }
    #undef ISSUE
    #undef CONSUME

    // tail: scale by SA, split to fp16 hi/lo, store as half2 per lane pair
    __half2* dhi = (__half2*)g_Ah + (((size_t)r * KDIM) >> 1) + lane;
    __half2* dlo = (__half2*)g_Al + (((size_t)r * KDIM) >> 1) + lane;
    #pragma unroll
    for (int t = 0; t < 8; t++) {
        float v0 = acc[2 * t] * SA, v1 = acc[2 * t + 1] * SA;
        __half h0 = __float2half_rn(v0);
        __half h1 = __float2half_rn(v1);
        __half l0 = __float2half_rn(v0 - __half2float(h0));
        __half l1 = __float2half_rn(v1 - __half2float(h1));
        dhi[t * 32] = __halves2half2(h0, h1);
        dlo[t * 32] = __halves2half2(l0, l1);
    }
}

// ===================== kernel 4: fp16 3-pass mma GEMM, 4-stage cp.async multistage (R13 config) =====================
// out[NPAD(64/CTA), 64] = (Ah+Al)(Bh+Bl)^T * 2^-14 + bias  (drop Al*Bl)
// 8 warps as 2(M) x 4(N); warp tile 32x16; KC=32 (2 k16-steps), 16 chunks, 4 stages
static constexpr int KC    = 32;               // k (halfs) per chunk
static constexpr int HST   = 40;               // smem row stride (halfs): 80B, conflict-free
static constexpr int F_MAT = 64 * HST;         // 2560 halfs per matrix tile
static constexpr int F_STG = 4 * F_MAT;        // Ah, Al, Bh, Bl
static constexpr int NCH   = KDIM / KC;        // 16 chunks
static constexpr int GEMM_SMEM = 4 * F_STG * 2;   // 81920 bytes -> 2 CTAs/SM

__global__ void __launch_bounds__(256, 2) k_gemm(const float* __restrict__ bias,
                                                 float* __restrict__ out) {
    extern __shared__ __half smh[];

    int tid = threadIdx.x;
    int warp = tid >> 5, lane = tid & 31;
    int gid = lane >> 2, tig = lane & 3;
    int warpM = warp >> 2, warpN = warp & 3;
    int m_base = warpM * 32;
    int n_base = warpN * 16;
    int m0 = blockIdx.x * 64;

    // ldmatrix lane->tile mapping
    int t3  = lane >> 3, rin = lane & 7;
    int a_row = ((t3 & 1) << 3) + rin;
    int a_k   = (t3 >> 1) << 3;
    int b_row = ((t3 >> 1) << 3) + rin;
    int b_k   = (t3 & 1) << 3;

    // staging: per matrix 64 rows x 64B; 256 threads -> 1 cp.async each
    int srow = tid >> 2, so8 = (tid & 3) * 8;

    float acc[2][2][4];
    #pragma unroll
    for (int mt = 0; mt < 2; mt++)
        #pragma unroll
        for (int nt = 0; nt < 2; nt++)
            #pragma unroll
            for (int j = 0; j < 4; j++) acc[mt][nt][j] = 0.f;

    #define STAGE(kc) do {                                                       \
        if ((kc) < NCH) {                                                        \
            __half* _st = smh + ((kc) & 3) * F_STG;                              \
            int _go = (kc) * KC + so8;                                           \
            uint32_t _so = srow * HST + so8;                                     \
            asm volatile("cp.async.ca.shared.global [%0], [%1], 16;"             \
                :: "r"(smem_u32(_st + _so)),                                     \
                   "l"(g_Ah + (size_t)(m0 + srow) * KDIM + _go) : "memory");     \
            asm volatile("cp.async.ca.shared.global [%0], [%1], 16;"             \
                :: "r"(smem_u32(_st + F_MAT + _so)),                             \
                   "l"(g_Al + (size_t)(m0 + srow) * KDIM + _go) : "memory");     \
            asm volatile("cp.async.ca.shared.global [%0], [%1], 16;"             \
                :: "r"(smem_u32(_st + 2 * F_MAT + _so)),                         \
                   "l"(g_Bh + srow * KDIM + _go) : "memory");                    \
            asm volatile("cp.async.ca.shared.global [%0], [%1], 16;"             \
                :: "r"(smem_u32(_st + 3 * F_MAT + _so)),                         \
                   "l"(g_Bl + srow * KDIM + _go) : "memory");                    \
        }                                                                        \
        asm volatile("cp.async.commit_group;" ::: "memory");                     \
    } while (0)

    // ---- prologue: stage chunks 0,1,2 ----
    STAGE(0);
    STAGE(1);
    STAGE(2);

    #pragma unroll 1
    for (int kc = 0; kc < NCH; kc++) {
        asm volatile("cp.async.wait_group 2;" ::: "memory");   // chunk kc complete
        __syncthreads();
        STAGE(kc + 3);                                         // slot (kc+3)&3, free

        const __half* st  = smh + (kc & 3) * F_STG;
        const __half* pAh = st;
        const __half* pAl = st + F_MAT;
        const __half* pBh = st + 2 * F_MAT;
        const __half* pBl = st + 3 * F_MAT;

        #pragma unroll
        for (int ks = 0; ks < 2; ks++) {
            int k0 = ks * 16;
            uint32_t ah[2][4], al[2][4], bh[4], bl[4];
            #pragma unroll
            for (int mt = 0; mt < 2; mt++) {
                int off = (m_base + mt * 16 + a_row) * HST + k0 + a_k;
                ldsm4(ah[mt], smem_u32(pAh + off));
                ldsm4(al[mt], smem_u32(pAl + off));
            }
            {
                int off = (n_base + b_row) * HST + k0 + b_k;
                ldsm4(bh, smem_u32(pBh + off));
                ldsm4(bl, smem_u32(pBl + off));
            }
            #pragma unroll
            for (int mt = 0; mt < 2; mt++)
                #pragma unroll
                for (int nt = 0; nt < 2; nt++) {
                    mma16(acc[mt][nt], ah[mt], &bh[nt * 2]);
                    mma16(acc[mt][nt], al[mt], &bh[nt * 2]);
                    mma16(acc[mt][nt], ah[mt], &bl[nt * 2]);
                }
        }
    }
    #undef STAGE

    // ---- epilogue: un-scale + bias + store ----
    #pragma unroll
    for (int mt = 0; mt < 2; mt++) {
        int r  = m0 + m_base + mt * 16 + gid;
        int r8 = r + 8;
        #pragma unroll
        for (int nt = 0; nt < 2; nt++) {
            int c = n_base + nt * 8 + tig * 2;
            float b0 = __ldg(bias + c), b1 = __ldg(bias + c + 1);
            if (r < NP) {
                float2 v = make_float2(acc[mt][nt][0] * INV_SAB + b0,
                                       acc[mt][nt][1] * INV_SAB + b1);
                *(float2*)(out + (size_t)r * 64 + c) = v;
            }
            if (r8 < NP) {
                float2 v = make_float2(acc[mt][nt][2] * INV_SAB + b0,
                                       acc[mt][nt][3] * INV_SAB + b1);
                *(float2*)(out + (size_t)r8 * 64 + c) = v;
            }
        }
    }
}

// ===================== launch =====================
extern "C" void kernel_launch(void* const* d_in, const int* in_sizes, int n_in,
                              void* d_out, int out_size) {
    const float* feat = (const float*)d_in[0];
    const int*   recv = (const int*)d_in[1];
    const float* rp   = (const float*)d_in[2];
    const float* ws   = (const float*)d_in[3];
    const int*   snd  = (const int*)d_in[4];
    const float* ker  = (const float*)d_in[5];
    const float* bias = (const float*)d_in[6];
    float* out = (float*)d_out;

    cudaFuncSetAttribute(k_gemm, cudaFuncAttributeMaxDynamicSharedMemorySize, GEMM_SMEM);

    k_prep<<<(NPAD + 255) / 256, 256>>>(ker);
    k_fill<<<(EDG + 255) / 256, 256>>>(recv, snd, rp, ws);
    k_phase1<<<NPAD / 2, 64>>>(feat);
    k_gemm<<<NPAD / 64, 256, GEMM_SMEM>>>(bias, out);
}